// round 13
// baseline (speedup 1.0000x reference)
#include <cuda_runtime.h>
#include <cstdint>

// Problem constants (fixed by setup_inputs)
#define LDIM 2048
#define DDIM 4096
#define KEXP 8
#define MPOS 1024
#define UPOS 1024
#define DPROJ 512
#define HHID 2048
#define EHDIM 16384   // KEXP * HHID

// ---------------------------------------------------------------------------
// Device-global scratch (no runtime allocation allowed)
// ---------------------------------------------------------------------------
__device__ float    g_A[(size_t)UPOS * EHDIM];    // anchors @ W1_top
__device__ float    g_B[(size_t)MPOS * EHDIM];    // masks   @ W1_bot
__device__ uint32_t g_G[(size_t)MPOS * EHDIM];    // tf32 bits of gated/combined gelu
__device__ uint32_t g_hM[(size_t)MPOS * DDIM];    // tf32 gathered mask rows of h
__device__ uint32_t g_hU[(size_t)UPOS * DDIM];    // tf32 gathered anchor rows of h
__device__ float    g_q[MPOS * DPROJ];
__device__ float    g_k[UPOS * DPROJ];
__device__ float    g_gate[MPOS * KEXP];
__device__ float    g_cmb[MPOS * 10];

// ---------------------------------------------------------------------------
// helpers
// ---------------------------------------------------------------------------
__device__ __forceinline__ uint32_t f2tf(float x) {
    uint32_t r;
    asm("cvt.rna.tf32.f32 %0, %1;" : "=r"(r) : "f"(x));
    return r;
}
__device__ __forceinline__ uint32_t smem_u32(const void* p) {
    uint32_t a;
    asm("{ .reg .u64 t; cvta.to.shared.u64 t, %1; cvt.u32.u64 %0, t; }" : "=r"(a) : "l"(p));
    return a;
}
__device__ __forceinline__ void cp16(uint32_t dst, const void* src) {
    asm volatile("cp.async.cg.shared.global [%0], [%1], 16;" :: "r"(dst), "l"(src));
}
#define CP_COMMIT() asm volatile("cp.async.commit_group;" ::: "memory")
#define CP_WAIT(n)  asm volatile("cp.async.wait_group %0;" :: "n"(n) : "memory")

__device__ __forceinline__ void ldsm_x4(uint32_t* r, uint32_t addr) {
    asm volatile("ldmatrix.sync.aligned.m8n8.x4.shared.b16 {%0,%1,%2,%3}, [%4];"
                 : "=r"(r[0]), "=r"(r[1]), "=r"(r[2]), "=r"(r[3]) : "r"(addr));
}

__device__ __forceinline__ void mma_tf32(float* c, const uint32_t* a, const uint32_t* b) {
    asm volatile(
        "mma.sync.aligned.m16n8k8.row.col.f32.tf32.tf32.f32 "
        "{%0,%1,%2,%3}, {%4,%5,%6,%7}, {%8,%9}, {%0,%1,%2,%3};\n"
        : "+f"(c[0]), "+f"(c[1]), "+f"(c[2]), "+f"(c[3])
        : "r"(a[0]), "r"(a[1]), "r"(a[2]), "r"(a[3]), "r"(b[0]), "r"(b[1]));
}

// smem stage layout (bytes):
//   A tile: [128 m][36 words]  rows 144 B (ldmatrix phases hit banks 4l..4l+3, CF)
//   B tile: [32 k][136 words]  rows 544 B (136 mod 32 = 8 -> banks 8tg+g, CF)
#define ALD 36
#define BLD 136
#define A_BYTES (128 * ALD * 4)          // 18432
#define B_BYTES (32 * BLD * 4)           // 17408
#define SM_STAGE (A_BYTES + B_BYTES)     // 35840
#define SM_TOTAL (3 * SM_STAGE)          // 107520

// ---------------------------------------------------------------------------
// Core tf32 GEMM tile: C[m0.., n0..] += A(m)[k] * W(k, n), K=Kdim.
// cp.async 3-stage pipeline (issues spread across ks steps), ldmatrix A loads,
// B scalar LDS + cvt; fragment registers double-buffered across ks steps.
// BM=BN=128, BK=32; 128 threads; 4 warps (2x2) each 64x64 via m16n8k8.
// ---------------------------------------------------------------------------
__device__ __forceinline__ void gemm_core(
    const uint32_t* __restrict__ Ag, int lda,
    const float* __restrict__ wbase, int ldw,
    float* __restrict__ Cg, int ldc, const int* __restrict__ rowC,
    int Kdim, int m0, int n0, char* smc)
{
    const int tid = threadIdx.x, lane = tid & 31, wid = tid >> 5;
    const uint32_t sb = smem_u32(smc);

    const int wm = (wid & 1) * 64, wn = (wid >> 1) * 64;
    const int g = lane >> 2, tg = lane & 3;

    const uint32_t aoff = (uint32_t)(wm + (lane & 15)) * (ALD * 4) + (lane >> 4) * 16;

    // A loader: rows ar+16i (i<8), 16B chunk akq
    const int ar = tid >> 3, akq = tid & 7;
    const uint32_t* aptr[8];
#pragma unroll
    for (int i = 0; i < 8; i++)
        aptr[i] = Ag + (size_t)(m0 + ar + 16 * i) * lda + akq * 4;
    // B loader: k rows bk+4i (i<8), 16B chunk bnq
    const int bk = tid >> 5, bnq = tid & 31;
    const float* bbase = wbase + (size_t)bk * ldw + bnq * 4;

// full-stage issue (prologue only)
#define ISSUE(s, kt)                                                             \
    {                                                                            \
        uint32_t ab = sb + (s) * SM_STAGE;                                       \
        _Pragma("unroll")                                                        \
        for (int i = 0; i < 8; i++)                                              \
            cp16(ab + (ar + 16 * i) * (ALD * 4) + akq * 16, aptr[i] + (kt));     \
        uint32_t bb = sb + (s) * SM_STAGE + A_BYTES;                             \
        _Pragma("unroll")                                                        \
        for (int i = 0; i < 8; i++)                                              \
            cp16(bb + (bk + 4 * i) * (BLD * 4) + bnq * 16,                       \
                 bbase + (size_t)((kt) + 4 * i) * ldw);                          \
        CP_COMMIT();                                                             \
    }

// quarter-stage issue (spread across ks steps; commit on part 3)
#define ISSUE_P(s, kt, p)                                                        \
    {                                                                            \
        uint32_t ab = sb + (s) * SM_STAGE;                                       \
        uint32_t bb = ab + A_BYTES;                                              \
        cp16(ab + (ar + 16 * (2 * (p))) * (ALD * 4) + akq * 16,                  \
             aptr[2 * (p)] + (kt));                                              \
        cp16(ab + (ar + 16 * (2 * (p) + 1)) * (ALD * 4) + akq * 16,              \
             aptr[2 * (p) + 1] + (kt));                                          \
        cp16(bb + (bk + 4 * (2 * (p))) * (BLD * 4) + bnq * 16,                   \
             bbase + (size_t)((kt) + 4 * (2 * (p))) * ldw);                      \
        cp16(bb + (bk + 4 * (2 * (p) + 1)) * (BLD * 4) + bnq * 16,               \
             bbase + (size_t)((kt) + 4 * (2 * (p) + 1)) * ldw);                  \
        if ((p) == 3) CP_COMMIT();                                               \
    }

// fragment loads for one ks step
#define LOADA(ks, arr)                                                           \
    { _Pragma("unroll")                                                          \
      for (int mf = 0; mf < 4; mf++)                                             \
          ldsm_x4((arr)[mf], abase + mf * (16 * ALD * 4) + (ks) * 32); }
#define LOADB(ks, arr)                                                           \
    { _Pragma("unroll")                                                          \
      for (int nf = 0; nf < 8; nf++) {                                           \
          int c = wn + nf * 8 + g;                                               \
          (arr)[nf][0] = f2tf(Bs[((ks) * 8 + tg) * BLD + c]);                    \
          (arr)[nf][1] = f2tf(Bs[((ks) * 8 + tg + 4) * BLD + c]);                \
      } }

    float acc[4][8][4];
#pragma unroll
    for (int i = 0; i < 4; i++)
#pragma unroll
        for (int j = 0; j < 8; j++)
#pragma unroll
            for (int c = 0; c < 4; c++) acc[i][j][c] = 0.f;

    const int KT = Kdim / 32;
    ISSUE(0, 0);
    ISSUE(1, 32);

    for (int ki = 0; ki < KT; ki++) {
        if (ki == KT - 1) { CP_WAIT(0); } else { CP_WAIT(1); }
        __syncthreads();
        const bool pre = (ki + 2 < KT);
        const int ps = (ki + 2) % 3;
        const int pk = (ki + 2) * 32;

        const uint32_t abase = sb + (ki % 3) * SM_STAGE + aoff;
        const float*   Bs = (const float*)(smc + (ki % 3) * SM_STAGE + A_BYTES);

        uint32_t a[2][4][4], b[2][8][2];
        LOADA(0, a[0]);
        LOADB(0, b[0]);
#pragma unroll
        for (int ks = 0; ks < 4; ks++) {
            const int cur = ks & 1, nxt = cur ^ 1;
            if (ks < 3) { LOADA(ks + 1, a[nxt]); LOADB(ks + 1, b[nxt]); }
            if (pre) ISSUE_P(ps, pk, ks);
#pragma unroll
            for (int mf = 0; mf < 4; mf++)
#pragma unroll
                for (int nf = 0; nf < 8; nf++)
                    mma_tf32(acc[mf][nf], a[cur][mf], b[cur][nf]);
        }
    }

#pragma unroll
    for (int mf = 0; mf < 4; mf++) {
        int r0 = m0 + wm + mf * 16 + g;
        int r1 = r0 + 8;
        size_t o0 = (size_t)(rowC ? rowC[r0] : r0) * (size_t)ldc;
        size_t o1 = (size_t)(rowC ? rowC[r1] : r1) * (size_t)ldc;
#pragma unroll
        for (int nf = 0; nf < 8; nf++) {
            int c = n0 + wn + nf * 8 + tg * 2;
            *reinterpret_cast<float2*>(Cg + o0 + c) = make_float2(acc[mf][nf][0], acc[mf][nf][1]);
            *reinterpret_cast<float2*>(Cg + o1 + c) = make_float2(acc[mf][nf][2], acc[mf][nf][3]);
        }
    }
#undef ISSUE
#undef ISSUE_P
#undef LOADA
#undef LOADB
}

// ---------------------------------------------------------------------------
// Generic GEMM (used for the final W2 GEMM, rowC = midx scatter)
// ---------------------------------------------------------------------------
__global__ __launch_bounds__(128, 2)
void gemm_cp(const uint32_t* __restrict__ Ag, int lda,
             const float* __restrict__ Wg, int ldw,
             float* __restrict__ Cg, int ldc, const int* __restrict__ rowC,
             int Kdim)
{
    extern __shared__ char smc[];
    const int m0 = blockIdx.x * 128, n0 = blockIdx.y * 128;
    gemm_core(Ag, lda, Wg + n0, ldw, Cg, ldc, rowC, Kdim, m0, n0, smc);
}

// ---------------------------------------------------------------------------
// Fused launch: z=0 -> A = hU @ W1_top ; z=1 -> B = hM @ W1_bot ;
//               z=2, y<4 -> q = hM @ Wq ; z=2, 4<=y<8 -> k = hU @ Wk.
// All slices share Kdim = DDIM = 4096.
// ---------------------------------------------------------------------------
__global__ __launch_bounds__(128, 2)
void gemm_fused(const uint32_t* __restrict__ hU, const uint32_t* __restrict__ hM,
                const float* __restrict__ W1,
                const float* __restrict__ Wq, const float* __restrict__ Wk,
                float* __restrict__ CA, float* __restrict__ CB,
                float* __restrict__ Cq, float* __restrict__ Ck)
{
    extern __shared__ char smc[];
    const int m0 = blockIdx.x * 128;
    const int z = blockIdx.z, y = blockIdx.y;
    const size_t ESTR = (size_t)2 * DDIM * HHID;

    if (z == 0) {
        int n0 = y * 128;
        const float* wb = W1 + (size_t)(n0 / HHID) * ESTR + (size_t)(n0 % HHID);
        gemm_core(hU, DDIM, wb, HHID, CA, EHDIM, nullptr, DDIM, m0, n0, smc);
    } else if (z == 1) {
        int n0 = y * 128;
        const float* wb = W1 + (size_t)DDIM * HHID
                        + (size_t)(n0 / HHID) * ESTR + (size_t)(n0 % HHID);
        gemm_core(hM, DDIM, wb, HHID, CB, EHDIM, nullptr, DDIM, m0, n0, smc);
    } else {
        if (y < 4) {
            int n0 = y * 128;
            gemm_core(hM, DDIM, Wq + n0, DPROJ, Cq, DPROJ, nullptr, DDIM, m0, n0, smc);
        } else if (y < 8) {
            int n0 = (y - 4) * 128;
            gemm_core(hU, DDIM, Wk + n0, DPROJ, Ck, DPROJ, nullptr, DDIM, m0, n0, smc);
        }
        // y >= 8: immediate exit
    }
}

// ---------------------------------------------------------------------------
// gather h rows by index + convert to tf32 bits; optionally (gate != nullptr)
// also compute gate[r,:] = softmax(h_row @ Wr + br) in the same pass.
// ---------------------------------------------------------------------------
__global__ void gather_gate(const float* __restrict__ h, const int* __restrict__ idx,
                            uint32_t* __restrict__ dst,
                            const float* __restrict__ Wr, const float* __restrict__ br,
                            float* __restrict__ gate)
{
    const int r = blockIdx.x;
    const int tid = threadIdx.x;
    const float4* s = reinterpret_cast<const float4*>(h + (size_t)idx[r] * DDIM);
    uint4* d = reinterpret_cast<uint4*>(dst + (size_t)r * DDIM);

    float acc[KEXP];
#pragma unroll
    for (int e = 0; e < KEXP; e++) acc[e] = 0.f;

    for (int i = tid; i < DDIM / 4; i += 256) {
        float4 v = s[i];
        uint4 o;
        o.x = f2tf(v.x); o.y = f2tf(v.y); o.z = f2tf(v.z); o.w = f2tf(v.w);
        d[i] = o;
        if (gate) {
            const float4* wr = reinterpret_cast<const float4*>(Wr + (size_t)(4 * i) * KEXP);
            float hv[4] = {v.x, v.y, v.z, v.w};
#pragma unroll
            for (int dd = 0; dd < 4; dd++) {
                float4 w0 = wr[2 * dd], w1 = wr[2 * dd + 1];
                acc[0] += hv[dd] * w0.x; acc[1] += hv[dd] * w0.y;
                acc[2] += hv[dd] * w0.z; acc[3] += hv[dd] * w0.w;
                acc[4] += hv[dd] * w1.x; acc[5] += hv[dd] * w1.y;
                acc[6] += hv[dd] * w1.z; acc[7] += hv[dd] * w1.w;
            }
        }
    }
    if (!gate) return;

#pragma unroll
    for (int off = 16; off > 0; off >>= 1)
#pragma unroll
        for (int e = 0; e < KEXP; e++)
            acc[e] += __shfl_down_sync(0xffffffffu, acc[e], off);

    __shared__ float ws[8][KEXP];
    const int w = tid >> 5, lane = tid & 31;
    if (lane == 0)
#pragma unroll
        for (int e = 0; e < KEXP; e++) ws[w][e] = acc[e];
    __syncthreads();
    if (tid == 0) {
        float l[KEXP];
#pragma unroll
        for (int e = 0; e < KEXP; e++) {
            float s2 = br[e];
#pragma unroll
            for (int ww = 0; ww < 8; ww++) s2 += ws[ww][e];
            l[e] = s2;
        }
        float mx = l[0];
#pragma unroll
        for (int e = 1; e < KEXP; e++) mx = fmaxf(mx, l[e]);
        float sum = 0.f;
#pragma unroll
        for (int e = 0; e < KEXP; e++) { l[e] = expf(l[e] - mx); sum += l[e]; }
        float inv = 1.f / sum;
#pragma unroll
        for (int e = 0; e < KEXP; e++) gate[r * KEXP + e] = l[e] * inv;
    }
}

// ---------------------------------------------------------------------------
// per-mask pair scores + segment softmax (anchors u = m-5 .. m+4 in [0,UPOS))
// float4 dot products.
// ---------------------------------------------------------------------------
__global__ void score_combine(const float* __restrict__ q, const float* __restrict__ k,
                              const float* __restrict__ bq, const float* __restrict__ bk,
                              float* __restrict__ cmb)
{
    const int m = blockIdx.x;
    const int w = threadIdx.x >> 5;    // 0..9
    const int lane = threadIdx.x & 31;
    const int u = m - 5 + w;
    const bool valid = (u >= 0) && (u < UPOS);

    __shared__ float sc[10];
    float s = 0.f;
    if (valid) {
        const float4* qp = reinterpret_cast<const float4*>(q + (size_t)m * DPROJ);
        const float4* kp = reinterpret_cast<const float4*>(k + (size_t)u * DPROJ);
        const float4* bqp = reinterpret_cast<const float4*>(bq);
        const float4* bkp = reinterpret_cast<const float4*>(bk);
#pragma unroll
        for (int i = lane; i < DPROJ / 4; i += 32) {
            float4 qv = qp[i], kv = kp[i], bqv = bqp[i], bkv = bkp[i];
            s += (qv.x + bqv.x) * (kv.x + bkv.x);
            s += (qv.y + bqv.y) * (kv.y + bkv.y);
            s += (qv.z + bqv.z) * (kv.z + bkv.z);
            s += (qv.w + bqv.w) * (kv.w + bkv.w);
        }
#pragma unroll
        for (int off = 16; off > 0; off >>= 1)
            s += __shfl_down_sync(0xffffffffu, s, off);
    }
    if (lane == 0) sc[w] = valid ? s * 0.044194173824159216f : -1e30f;
    __syncthreads();
    if (threadIdx.x == 0) {
        float mx = -1e30f;
#pragma unroll
        for (int j = 0; j < 10; j++) mx = fmaxf(mx, sc[j]);
        float e[10]; float sum = 0.f;
#pragma unroll
        for (int j = 0; j < 10; j++) {
            e[j] = (sc[j] > -1e29f) ? expf(sc[j] - mx) : 0.f;
            sum += e[j];
        }
        float inv = 1.f / fmaxf(sum, 1e-8f);
#pragma unroll
        for (int j = 0; j < 10; j++) cmb[m * 10 + j] = e[j] * inv;
    }
}

// ---------------------------------------------------------------------------
// g_G[m, n] = tf32( gate[m][n/H] * sum_j cmb[m][j] * gelu(A[u_j,n]+B[m,n]+b1[n]) )
// 4 masks per block (m-tiling): A rows m0-5..m0+8 held in registers, reused
// across the 4 masks -> ~2.9x less A traffic. float4 per thread.
// ---------------------------------------------------------------------------
__global__ __launch_bounds__(256)
void aggregate_kernel(const float* __restrict__ A, const float* __restrict__ B,
                      const float* __restrict__ b1, const float* __restrict__ cmb,
                      const float* __restrict__ gate, uint32_t* __restrict__ G)
{
    const int m0 = blockIdx.y * 4;
    const int n4 = blockIdx.x * 256 + threadIdx.x;   // float4 index
    const int n = n4 * 4;

    __shared__ float c[4][10];
    __shared__ float gt[4][KEXP];
    if (threadIdx.x < 40)
        c[threadIdx.x / 10][threadIdx.x % 10] = cmb[(m0 + threadIdx.x / 10) * 10 + threadIdx.x % 10];
    if (threadIdx.x >= 64 && threadIdx.x < 96) {
        int t = threadIdx.x - 64;
        gt[t / 8][t % 8] = gate[(m0 + t / 8) * KEXP + t % 8];
    }
    __syncthreads();

    // A rows u = clip(m0-5+i), i in [0,14)
    float4 av[14];
#pragma unroll
    for (int i = 0; i < 14; i++) {
        int u = min(max(m0 - 5 + i, 0), UPOS - 1);
        av[i] = reinterpret_cast<const float4*>(A + (size_t)u * EHDIM)[n4];
    }
    const float4 b1q = reinterpret_cast<const float4*>(b1)[n4];
    const int eidx = n >> 11;

#pragma unroll
    for (int mm = 0; mm < 4; mm++) {
        const int m = m0 + mm;
        const float4 Bq = reinterpret_cast<const float4*>(B + (size_t)m * EHDIM)[n4];
        float Bv[4] = {Bq.x + b1q.x, Bq.y + b1q.y, Bq.z + b1q.z, Bq.w + b1q.w};
        float acc[4] = {0.f, 0.f, 0.f, 0.f};
#pragma unroll
        for (int j = 0; j < 10; j++) {
            const float4 Aq = av[mm + j];
            float avx[4] = {Aq.x, Aq.y, Aq.z, Aq.w};
#pragma unroll
            for (int d = 0; d < 4; d++) {
                float x = avx[d] + Bv[d];
                float ge = 0.5f * x * (1.f + erff(x * 0.70710678118654752f));
                acc[d] = fmaf(c[mm][j], ge, acc[d]);
            }
        }
        const float gv = gt[mm][eidx];
        uint4 o;
        o.x = f2tf(gv * acc[0]); o.y = f2tf(gv * acc[1]);
        o.z = f2tf(gv * acc[2]); o.w = f2tf(gv * acc[3]);
        reinterpret_cast<uint4*>(G + (size_t)m * EHDIM)[n4] = o;
    }
}

// out[midx[m], d..d+3] += sum_e gate[m][e] * b2[e][d..d+3]
__global__ void addb2_kernel(const float* __restrict__ gate, const float* __restrict__ b2,
                             const int* __restrict__ midx, float* __restrict__ out)
{
    const int m = blockIdx.y;
    const int d4 = blockIdx.x * 256 + threadIdx.x;
    float4 s = make_float4(0.f, 0.f, 0.f, 0.f);
#pragma unroll
    for (int e = 0; e < KEXP; e++) {
        float ge = gate[m * KEXP + e];
        float4 bq = reinterpret_cast<const float4*>(b2 + (size_t)e * DDIM)[d4];
        s.x = fmaf(ge, bq.x, s.x); s.y = fmaf(ge, bq.y, s.y);
        s.z = fmaf(ge, bq.z, s.z); s.w = fmaf(ge, bq.w, s.w);
    }
    float4* op = &reinterpret_cast<float4*>(out + (size_t)midx[m] * DDIM)[d4];
    float4 cur = *op;
    cur.x += s.x; cur.y += s.y; cur.z += s.z; cur.w += s.w;
    *op = cur;
}

// ---------------------------------------------------------------------------
extern "C" void kernel_launch(void* const* d_in, const int* in_sizes, int n_in,
                              void* d_out, int out_size)
{
    const float* h   = (const float*)d_in[0];
    const int*   midx= (const int*)d_in[1];
    const int*   uidx= (const int*)d_in[2];
    const float* Wr  = (const float*)d_in[4];
    const float* br  = (const float*)d_in[5];
    const float* W1  = (const float*)d_in[6];
    const float* b1  = (const float*)d_in[7];
    const float* W2  = (const float*)d_in[8];
    const float* b2  = (const float*)d_in[9];
    const float* Wq  = (const float*)d_in[10];
    const float* bq  = (const float*)d_in[11];
    const float* Wk  = (const float*)d_in[12];
    const float* bk  = (const float*)d_in[13];
    float* out = (float*)d_out;

    float *pA, *pB, *pq, *pk, *pgate, *pcmb;
    uint32_t *pG, *phM, *phU;
    cudaGetSymbolAddress((void**)&pA, g_A);
    cudaGetSymbolAddress((void**)&pB, g_B);
    cudaGetSymbolAddress((void**)&pG, g_G);
    cudaGetSymbolAddress((void**)&phM, g_hM);
    cudaGetSymbolAddress((void**)&phU, g_hU);
    cudaGetSymbolAddress((void**)&pq, g_q);
    cudaGetSymbolAddress((void**)&pk, g_k);
    cudaGetSymbolAddress((void**)&pgate, g_gate);
    cudaGetSymbolAddress((void**)&pcmb, g_cmb);

    cudaFuncSetAttribute(gemm_cp, cudaFuncAttributeMaxDynamicSharedMemorySize, SM_TOTAL);
    cudaFuncSetAttribute(gemm_fused, cudaFuncAttributeMaxDynamicSharedMemorySize, SM_TOTAL);

    // zero output (odd rows stay zero; even rows overwritten by final GEMM)
    cudaMemsetAsync(out, 0, (size_t)out_size * sizeof(float));

    // gather + convert h rows; mask variant also computes the gate softmax
    gather_gate<<<MPOS, 256>>>(h, midx, phM, Wr, br, pgate);
    gather_gate<<<UPOS, 256>>>(h, uidx, phU, nullptr, nullptr, nullptr);

    // Fused: z=0 -> A = hU @ W1_top ; z=1 -> B = hM @ W1_bot ; z=2 -> q/k GEMMs
    gemm_fused<<<dim3(MPOS / 128, EHDIM / 128, 3), 128, SM_TOTAL>>>(
        phU, phM, W1, Wq, Wk, pA, pB, pq, pk);

    // per-mask segment softmax over <=10 anchors
    score_combine<<<MPOS, 320>>>(pq, pk, bq, bk, pcmb);

    // gelu + combine aggregation, gate folded in, tf32 output (float4, 4 masks/block)
    aggregate_kernel<<<dim3(EHDIM / 1024, MPOS / 4), 256>>>(pA, pB, b1, pcmb, pgate, pG);

    // out[masks] = G @ W2_flat   (K = 16384, W2 flat contiguous [16384 x 4096])
    gemm_cp<<<dim3(MPOS / 128, DDIM / 128, 1), 128, SM_TOTAL>>>(
        pG, EHDIM, W2, DDIM, out, DDIM, midx, EHDIM);

    // + sum_e gate*b2 (combine weights sum to 1 per mask)
    addb2_kernel<<<dim3(DDIM / 1024, MPOS), 256>>>(pgate, b2, midx, out);
}

// round 14
// speedup vs baseline: 1.1570x; 1.1570x over previous
#include <cuda_runtime.h>
#include <cstdint>

// Problem constants (fixed by setup_inputs)
#define LDIM 2048
#define DDIM 4096
#define KEXP 8
#define MPOS 1024
#define UPOS 1024
#define DPROJ 512
#define HHID 2048
#define EHDIM 16384   // KEXP * HHID

// ---------------------------------------------------------------------------
// Device-global scratch (no runtime allocation allowed)
// ---------------------------------------------------------------------------
__device__ float    g_A[(size_t)UPOS * EHDIM];    // anchors @ W1_top
__device__ float    g_B[(size_t)MPOS * EHDIM];    // masks   @ W1_bot
__device__ uint32_t g_G[(size_t)MPOS * EHDIM];    // tf32 bits of gated/combined gelu
__device__ uint32_t g_hM[(size_t)MPOS * DDIM];    // tf32 gathered mask rows of h
__device__ uint32_t g_hU[(size_t)UPOS * DDIM];    // tf32 gathered anchor rows of h
__device__ float    g_q[MPOS * DPROJ];
__device__ float    g_k[UPOS * DPROJ];
__device__ float    g_gate[MPOS * KEXP];
__device__ float    g_cmb[MPOS * 10];

// ---------------------------------------------------------------------------
// helpers
// ---------------------------------------------------------------------------
__device__ __forceinline__ uint32_t f2tf(float x) {
    uint32_t r;
    asm("cvt.rna.tf32.f32 %0, %1;" : "=r"(r) : "f"(x));
    return r;
}
__device__ __forceinline__ uint32_t smem_u32(const void* p) {
    uint32_t a;
    asm("{ .reg .u64 t; cvta.to.shared.u64 t, %1; cvt.u32.u64 %0, t; }" : "=r"(a) : "l"(p));
    return a;
}
__device__ __forceinline__ void cp16(uint32_t dst, const void* src) {
    asm volatile("cp.async.cg.shared.global [%0], [%1], 16;" :: "r"(dst), "l"(src));
}
#define CP_COMMIT() asm volatile("cp.async.commit_group;" ::: "memory")
#define CP_WAIT(n)  asm volatile("cp.async.wait_group %0;" :: "n"(n) : "memory")

__device__ __forceinline__ void ldsm_x4(uint32_t* r, uint32_t addr) {
    asm volatile("ldmatrix.sync.aligned.m8n8.x4.shared.b16 {%0,%1,%2,%3}, [%4];"
                 : "=r"(r[0]), "=r"(r[1]), "=r"(r[2]), "=r"(r[3]) : "r"(addr));
}

__device__ __forceinline__ void mma_tf32(float* c, const uint32_t* a, const uint32_t* b) {
    asm volatile(
        "mma.sync.aligned.m16n8k8.row.col.f32.tf32.tf32.f32 "
        "{%0,%1,%2,%3}, {%4,%5,%6,%7}, {%8,%9}, {%0,%1,%2,%3};\n"
        : "+f"(c[0]), "+f"(c[1]), "+f"(c[2]), "+f"(c[3])
        : "r"(a[0]), "r"(a[1]), "r"(a[2]), "r"(a[3]), "r"(b[0]), "r"(b[1]));
}

// smem stage layout (bytes):
//   A tile: [128 m][36 words]  rows 144 B (ldmatrix phases hit banks 4l..4l+3, CF)
//   B tile: [32 k][136 words]  rows 544 B (136 mod 32 = 8 -> banks 8tg+g, CF)
#define ALD 36
#define BLD 136
#define A_BYTES (128 * ALD * 4)          // 18432
#define B_BYTES (32 * BLD * 4)           // 17408
#define SM_STAGE (A_BYTES + B_BYTES)     // 35840
#define SM_TOTAL (3 * SM_STAGE)          // 107520

// ---------------------------------------------------------------------------
// Core tf32 GEMM tile: C[m0.., n0..] += A(m)[k] * W(k, n), K=Kdim.
// cp.async 3-stage pipeline (issues spread across ks steps), ldmatrix A loads,
// B scalar LDS + cvt; fragment registers double-buffered across ks steps.
// BM=BN=128, BK=32; 128 threads; 4 warps (2x2) each 64x64 via m16n8k8.
// ---------------------------------------------------------------------------
__device__ __forceinline__ void gemm_core(
    const uint32_t* __restrict__ Ag, int lda,
    const float* __restrict__ wbase, int ldw,
    float* __restrict__ Cg, int ldc, const int* __restrict__ rowC,
    int Kdim, int m0, int n0, char* smc)
{
    const int tid = threadIdx.x, lane = tid & 31, wid = tid >> 5;
    const uint32_t sb = smem_u32(smc);

    const int wm = (wid & 1) * 64, wn = (wid >> 1) * 64;
    const int g = lane >> 2, tg = lane & 3;

    const uint32_t aoff = (uint32_t)(wm + (lane & 15)) * (ALD * 4) + (lane >> 4) * 16;

    // A loader: rows ar+16i (i<8), 16B chunk akq
    const int ar = tid >> 3, akq = tid & 7;
    const uint32_t* aptr[8];
#pragma unroll
    for (int i = 0; i < 8; i++)
        aptr[i] = Ag + (size_t)(m0 + ar + 16 * i) * lda + akq * 4;
    // B loader: k rows bk+4i (i<8), 16B chunk bnq
    const int bk = tid >> 5, bnq = tid & 31;
    const float* bbase = wbase + (size_t)bk * ldw + bnq * 4;

// full-stage issue (prologue only)
#define ISSUE(s, kt)                                                             \
    {                                                                            \
        uint32_t ab = sb + (s) * SM_STAGE;                                       \
        _Pragma("unroll")                                                        \
        for (int i = 0; i < 8; i++)                                              \
            cp16(ab + (ar + 16 * i) * (ALD * 4) + akq * 16, aptr[i] + (kt));     \
        uint32_t bb = sb + (s) * SM_STAGE + A_BYTES;                             \
        _Pragma("unroll")                                                        \
        for (int i = 0; i < 8; i++)                                              \
            cp16(bb + (bk + 4 * i) * (BLD * 4) + bnq * 16,                       \
                 bbase + (size_t)((kt) + 4 * i) * ldw);                          \
        CP_COMMIT();                                                             \
    }

// quarter-stage issue (spread across ks steps; commit on part 3)
#define ISSUE_P(s, kt, p)                                                        \
    {                                                                            \
        uint32_t ab = sb + (s) * SM_STAGE;                                       \
        uint32_t bb = ab + A_BYTES;                                              \
        cp16(ab + (ar + 16 * (2 * (p))) * (ALD * 4) + akq * 16,                  \
             aptr[2 * (p)] + (kt));                                              \
        cp16(ab + (ar + 16 * (2 * (p) + 1)) * (ALD * 4) + akq * 16,              \
             aptr[2 * (p) + 1] + (kt));                                          \
        cp16(bb + (bk + 4 * (2 * (p))) * (BLD * 4) + bnq * 16,                   \
             bbase + (size_t)((kt) + 4 * (2 * (p))) * ldw);                      \
        cp16(bb + (bk + 4 * (2 * (p) + 1)) * (BLD * 4) + bnq * 16,               \
             bbase + (size_t)((kt) + 4 * (2 * (p) + 1)) * ldw);                  \
        if ((p) == 3) CP_COMMIT();                                               \
    }

// fragment loads for one ks step
#define LOADA(ks, arr)                                                           \
    { _Pragma("unroll")                                                          \
      for (int mf = 0; mf < 4; mf++)                                             \
          ldsm_x4((arr)[mf], abase + mf * (16 * ALD * 4) + (ks) * 32); }
#define LOADB(ks, arr)                                                           \
    { _Pragma("unroll")                                                          \
      for (int nf = 0; nf < 8; nf++) {                                           \
          int c = wn + nf * 8 + g;                                               \
          (arr)[nf][0] = f2tf(Bs[((ks) * 8 + tg) * BLD + c]);                    \
          (arr)[nf][1] = f2tf(Bs[((ks) * 8 + tg + 4) * BLD + c]);                \
      } }

    float acc[4][8][4];
#pragma unroll
    for (int i = 0; i < 4; i++)
#pragma unroll
        for (int j = 0; j < 8; j++)
#pragma unroll
            for (int c = 0; c < 4; c++) acc[i][j][c] = 0.f;

    const int KT = Kdim / 32;
    ISSUE(0, 0);
    ISSUE(1, 32);

    for (int ki = 0; ki < KT; ki++) {
        if (ki == KT - 1) { CP_WAIT(0); } else { CP_WAIT(1); }
        __syncthreads();
        const bool pre = (ki + 2 < KT);
        const int ps = (ki + 2) % 3;
        const int pk = (ki + 2) * 32;

        const uint32_t abase = sb + (ki % 3) * SM_STAGE + aoff;
        const float*   Bs = (const float*)(smc + (ki % 3) * SM_STAGE + A_BYTES);

        uint32_t a[2][4][4], b[2][8][2];
        LOADA(0, a[0]);
        LOADB(0, b[0]);
#pragma unroll
        for (int ks = 0; ks < 4; ks++) {
            const int cur = ks & 1, nxt = cur ^ 1;
            if (ks < 3) { LOADA(ks + 1, a[nxt]); LOADB(ks + 1, b[nxt]); }
            if (pre) ISSUE_P(ps, pk, ks);
#pragma unroll
            for (int mf = 0; mf < 4; mf++)
#pragma unroll
                for (int nf = 0; nf < 8; nf++)
                    mma_tf32(acc[mf][nf], a[cur][mf], b[cur][nf]);
        }
    }

#pragma unroll
    for (int mf = 0; mf < 4; mf++) {
        int r0 = m0 + wm + mf * 16 + g;
        int r1 = r0 + 8;
        size_t o0 = (size_t)(rowC ? rowC[r0] : r0) * (size_t)ldc;
        size_t o1 = (size_t)(rowC ? rowC[r1] : r1) * (size_t)ldc;
#pragma unroll
        for (int nf = 0; nf < 8; nf++) {
            int c = n0 + wn + nf * 8 + tg * 2;
            *reinterpret_cast<float2*>(Cg + o0 + c) = make_float2(acc[mf][nf][0], acc[mf][nf][1]);
            *reinterpret_cast<float2*>(Cg + o1 + c) = make_float2(acc[mf][nf][2], acc[mf][nf][3]);
        }
    }
#undef ISSUE
#undef ISSUE_P
#undef LOADA
#undef LOADB
}

// ---------------------------------------------------------------------------
// Generic GEMM (used for the final W2 GEMM, rowC = midx scatter)
// ---------------------------------------------------------------------------
__global__ __launch_bounds__(128, 2)
void gemm_cp(const uint32_t* __restrict__ Ag, int lda,
             const float* __restrict__ Wg, int ldw,
             float* __restrict__ Cg, int ldc, const int* __restrict__ rowC,
             int Kdim)
{
    extern __shared__ char smc[];
    const int m0 = blockIdx.x * 128, n0 = blockIdx.y * 128;
    gemm_core(Ag, lda, Wg + n0, ldw, Cg, ldc, rowC, Kdim, m0, n0, smc);
}

// ---------------------------------------------------------------------------
// Fused launch: z=0 -> A = hU @ W1_top ; z=1 -> B = hM @ W1_bot ;
//               z=2, y<4 -> q = hM @ Wq ; z=2, 4<=y<8 -> k = hU @ Wk.
// All slices share Kdim = DDIM = 4096.
// ---------------------------------------------------------------------------
__global__ __launch_bounds__(128, 2)
void gemm_fused(const uint32_t* __restrict__ hU, const uint32_t* __restrict__ hM,
                const float* __restrict__ W1,
                const float* __restrict__ Wq, const float* __restrict__ Wk,
                float* __restrict__ CA, float* __restrict__ CB,
                float* __restrict__ Cq, float* __restrict__ Ck)
{
    extern __shared__ char smc[];
    const int m0 = blockIdx.x * 128;
    const int z = blockIdx.z, y = blockIdx.y;
    const size_t ESTR = (size_t)2 * DDIM * HHID;

    if (z == 0) {
        int n0 = y * 128;
        const float* wb = W1 + (size_t)(n0 / HHID) * ESTR + (size_t)(n0 % HHID);
        gemm_core(hU, DDIM, wb, HHID, CA, EHDIM, nullptr, DDIM, m0, n0, smc);
    } else if (z == 1) {
        int n0 = y * 128;
        const float* wb = W1 + (size_t)DDIM * HHID
                        + (size_t)(n0 / HHID) * ESTR + (size_t)(n0 % HHID);
        gemm_core(hM, DDIM, wb, HHID, CB, EHDIM, nullptr, DDIM, m0, n0, smc);
    } else {
        if (y < 4) {
            int n0 = y * 128;
            gemm_core(hM, DDIM, Wq + n0, DPROJ, Cq, DPROJ, nullptr, DDIM, m0, n0, smc);
        } else if (y < 8) {
            int n0 = (y - 4) * 128;
            gemm_core(hU, DDIM, Wk + n0, DPROJ, Ck, DPROJ, nullptr, DDIM, m0, n0, smc);
        }
        // y >= 8: immediate exit
    }
}

// ---------------------------------------------------------------------------
// gather h rows by index + convert to tf32 bits; optionally (gate != nullptr)
// also compute gate[r,:] = softmax(h_row @ Wr + br) in the same pass.
// ---------------------------------------------------------------------------
__global__ void gather_gate(const float* __restrict__ h, const int* __restrict__ idx,
                            uint32_t* __restrict__ dst,
                            const float* __restrict__ Wr, const float* __restrict__ br,
                            float* __restrict__ gate)
{
    const int r = blockIdx.x;
    const int tid = threadIdx.x;
    const float4* s = reinterpret_cast<const float4*>(h + (size_t)idx[r] * DDIM);
    uint4* d = reinterpret_cast<uint4*>(dst + (size_t)r * DDIM);

    float acc[KEXP];
#pragma unroll
    for (int e = 0; e < KEXP; e++) acc[e] = 0.f;

    for (int i = tid; i < DDIM / 4; i += 256) {
        float4 v = s[i];
        uint4 o;
        o.x = f2tf(v.x); o.y = f2tf(v.y); o.z = f2tf(v.z); o.w = f2tf(v.w);
        d[i] = o;
        if (gate) {
            const float4* wr = reinterpret_cast<const float4*>(Wr + (size_t)(4 * i) * KEXP);
            float hv[4] = {v.x, v.y, v.z, v.w};
#pragma unroll
            for (int dd = 0; dd < 4; dd++) {
                float4 w0 = wr[2 * dd], w1 = wr[2 * dd + 1];
                acc[0] += hv[dd] * w0.x; acc[1] += hv[dd] * w0.y;
                acc[2] += hv[dd] * w0.z; acc[3] += hv[dd] * w0.w;
                acc[4] += hv[dd] * w1.x; acc[5] += hv[dd] * w1.y;
                acc[6] += hv[dd] * w1.z; acc[7] += hv[dd] * w1.w;
            }
        }
    }
    if (!gate) return;

#pragma unroll
    for (int off = 16; off > 0; off >>= 1)
#pragma unroll
        for (int e = 0; e < KEXP; e++)
            acc[e] += __shfl_down_sync(0xffffffffu, acc[e], off);

    __shared__ float ws[8][KEXP];
    const int w = tid >> 5, lane = tid & 31;
    if (lane == 0)
#pragma unroll
        for (int e = 0; e < KEXP; e++) ws[w][e] = acc[e];
    __syncthreads();
    if (tid == 0) {
        float l[KEXP];
#pragma unroll
        for (int e = 0; e < KEXP; e++) {
            float s2 = br[e];
#pragma unroll
            for (int ww = 0; ww < 8; ww++) s2 += ws[ww][e];
            l[e] = s2;
        }
        float mx = l[0];
#pragma unroll
        for (int e = 1; e < KEXP; e++) mx = fmaxf(mx, l[e]);
        float sum = 0.f;
#pragma unroll
        for (int e = 0; e < KEXP; e++) { l[e] = expf(l[e] - mx); sum += l[e]; }
        float inv = 1.f / sum;
#pragma unroll
        for (int e = 0; e < KEXP; e++) gate[r * KEXP + e] = l[e] * inv;
    }
}

// ---------------------------------------------------------------------------
// per-mask pair scores + segment softmax (anchors u = m-5 .. m+4 in [0,UPOS))
// float4 dot products.
// ---------------------------------------------------------------------------
__global__ void score_combine(const float* __restrict__ q, const float* __restrict__ k,
                              const float* __restrict__ bq, const float* __restrict__ bk,
                              float* __restrict__ cmb)
{
    const int m = blockIdx.x;
    const int w = threadIdx.x >> 5;    // 0..9
    const int lane = threadIdx.x & 31;
    const int u = m - 5 + w;
    const bool valid = (u >= 0) && (u < UPOS);

    __shared__ float sc[10];
    float s = 0.f;
    if (valid) {
        const float4* qp = reinterpret_cast<const float4*>(q + (size_t)m * DPROJ);
        const float4* kp = reinterpret_cast<const float4*>(k + (size_t)u * DPROJ);
        const float4* bqp = reinterpret_cast<const float4*>(bq);
        const float4* bkp = reinterpret_cast<const float4*>(bk);
#pragma unroll
        for (int i = lane; i < DPROJ / 4; i += 32) {
            float4 qv = qp[i], kv = kp[i], bqv = bqp[i], bkv = bkp[i];
            s += (qv.x + bqv.x) * (kv.x + bkv.x);
            s += (qv.y + bqv.y) * (kv.y + bkv.y);
            s += (qv.z + bqv.z) * (kv.z + bkv.z);
            s += (qv.w + bqv.w) * (kv.w + bkv.w);
        }
#pragma unroll
        for (int off = 16; off > 0; off >>= 1)
            s += __shfl_down_sync(0xffffffffu, s, off);
    }
    if (lane == 0) sc[w] = valid ? s * 0.044194173824159216f : -1e30f;
    __syncthreads();
    if (threadIdx.x == 0) {
        float mx = -1e30f;
#pragma unroll
        for (int j = 0; j < 10; j++) mx = fmaxf(mx, sc[j]);
        float e[10]; float sum = 0.f;
#pragma unroll
        for (int j = 0; j < 10; j++) {
            e[j] = (sc[j] > -1e29f) ? expf(sc[j] - mx) : 0.f;
            sum += e[j];
        }
        float inv = 1.f / fmaxf(sum, 1e-8f);
#pragma unroll
        for (int j = 0; j < 10; j++) cmb[m * 10 + j] = e[j] * inv;
    }
}

// ---------------------------------------------------------------------------
// g_G[m, n] = tf32( gate[m][n/H] * sum_j cmb[m][j] * gelu(A[u_j,n]+B[m,n]+b1[n]) )
// float4-vectorized: each thread handles 4 consecutive n. (R12 version)
// ---------------------------------------------------------------------------
__global__ void aggregate_kernel(const float* __restrict__ A, const float* __restrict__ B,
                                 const float* __restrict__ b1, const float* __restrict__ cmb,
                                 const float* __restrict__ gate, uint32_t* __restrict__ G)
{
    const int m = blockIdx.y;
    const int n4 = blockIdx.x * 256 + threadIdx.x;   // float4 index
    const int n = n4 * 4;
    __shared__ float c[10];
    __shared__ int   us[10];
    __shared__ float gt[KEXP];
    if (threadIdx.x < 10) {
        c[threadIdx.x] = cmb[m * 10 + threadIdx.x];
        int u = m - 5 + threadIdx.x;
        us[threadIdx.x] = min(max(u, 0), UPOS - 1);
    }
    if (threadIdx.x < KEXP) gt[threadIdx.x] = gate[m * KEXP + threadIdx.x];
    __syncthreads();

    const float4 Bq = reinterpret_cast<const float4*>(B + (size_t)m * EHDIM)[n4];
    const float4 b1q = reinterpret_cast<const float4*>(b1)[n4];
    float Bv[4] = {Bq.x + b1q.x, Bq.y + b1q.y, Bq.z + b1q.z, Bq.w + b1q.w};
    float acc[4] = {0.f, 0.f, 0.f, 0.f};
#pragma unroll
    for (int j = 0; j < 10; j++) {
        const float4 Aq = reinterpret_cast<const float4*>(A + (size_t)us[j] * EHDIM)[n4];
        float av[4] = {Aq.x, Aq.y, Aq.z, Aq.w};
#pragma unroll
        for (int d = 0; d < 4; d++) {
            float x = av[d] + Bv[d];
            float ge = 0.5f * x * (1.f + erff(x * 0.70710678118654752f));
            acc[d] = fmaf(c[j], ge, acc[d]);
        }
    }
    const float gv = gt[n >> 11];  // 4 consecutive n share the expert (4 | 2048)
    uint4 o;
    o.x = f2tf(gv * acc[0]); o.y = f2tf(gv * acc[1]);
    o.z = f2tf(gv * acc[2]); o.w = f2tf(gv * acc[3]);
    reinterpret_cast<uint4*>(G + (size_t)m * EHDIM)[n4] = o;
}

// out[midx[m], d..d+3] += sum_e gate[m][e] * b2[e][d..d+3]
__global__ void addb2_kernel(const float* __restrict__ gate, const float* __restrict__ b2,
                             const int* __restrict__ midx, float* __restrict__ out)
{
    const int m = blockIdx.y;
    const int d4 = blockIdx.x * 256 + threadIdx.x;
    float4 s = make_float4(0.f, 0.f, 0.f, 0.f);
#pragma unroll
    for (int e = 0; e < KEXP; e++) {
        float ge = gate[m * KEXP + e];
        float4 bq = reinterpret_cast<const float4*>(b2 + (size_t)e * DDIM)[d4];
        s.x = fmaf(ge, bq.x, s.x); s.y = fmaf(ge, bq.y, s.y);
        s.z = fmaf(ge, bq.z, s.z); s.w = fmaf(ge, bq.w, s.w);
    }
    float4* op = &reinterpret_cast<float4*>(out + (size_t)midx[m] * DDIM)[d4];
    float4 cur = *op;
    cur.x += s.x; cur.y += s.y; cur.z += s.z; cur.w += s.w;
    *op = cur;
}

// ---------------------------------------------------------------------------
extern "C" void kernel_launch(void* const* d_in, const int* in_sizes, int n_in,
                              void* d_out, int out_size)
{
    const float* h   = (const float*)d_in[0];
    const int*   midx= (const int*)d_in[1];
    const int*   uidx= (const int*)d_in[2];
    const float* Wr  = (const float*)d_in[4];
    const float* br  = (const float*)d_in[5];
    const float* W1  = (const float*)d_in[6];
    const float* b1  = (const float*)d_in[7];
    const float* W2  = (const float*)d_in[8];
    const float* b2  = (const float*)d_in[9];
    const float* Wq  = (const float*)d_in[10];
    const float* bq  = (const float*)d_in[11];
    const float* Wk  = (const float*)d_in[12];
    const float* bk  = (const float*)d_in[13];
    float* out = (float*)d_out;

    float *pA, *pB, *pq, *pk, *pgate, *pcmb;
    uint32_t *pG, *phM, *phU;
    cudaGetSymbolAddress((void**)&pA, g_A);
    cudaGetSymbolAddress((void**)&pB, g_B);
    cudaGetSymbolAddress((void**)&pG, g_G);
    cudaGetSymbolAddress((void**)&phM, g_hM);
    cudaGetSymbolAddress((void**)&phU, g_hU);
    cudaGetSymbolAddress((void**)&pq, g_q);
    cudaGetSymbolAddress((void**)&pk, g_k);
    cudaGetSymbolAddress((void**)&pgate, g_gate);
    cudaGetSymbolAddress((void**)&pcmb, g_cmb);

    cudaFuncSetAttribute(gemm_cp, cudaFuncAttributeMaxDynamicSharedMemorySize, SM_TOTAL);
    cudaFuncSetAttribute(gemm_fused, cudaFuncAttributeMaxDynamicSharedMemorySize, SM_TOTAL);

    // zero output (odd rows stay zero; even rows overwritten by final GEMM)
    cudaMemsetAsync(out, 0, (size_t)out_size * sizeof(float));

    // gather + convert h rows; mask variant also computes the gate softmax
    gather_gate<<<MPOS, 256>>>(h, midx, phM, Wr, br, pgate);
    gather_gate<<<UPOS, 256>>>(h, uidx, phU, nullptr, nullptr, nullptr);

    // Fused: z=0 -> A = hU @ W1_top ; z=1 -> B = hM @ W1_bot ; z=2 -> q/k GEMMs
    gemm_fused<<<dim3(MPOS / 128, EHDIM / 128, 3), 128, SM_TOTAL>>>(
        phU, phM, W1, Wq, Wk, pA, pB, pq, pk);

    // per-mask segment softmax over <=10 anchors
    score_combine<<<MPOS, 320>>>(pq, pk, bq, bk, pcmb);

    // gelu + combine aggregation, gate folded in, tf32 output (float4)
    aggregate_kernel<<<dim3(EHDIM / 1024, MPOS), 256>>>(pA, pB, b1, pcmb, pgate, pG);

    // out[masks] = G @ W2_flat   (K = 16384, W2 flat contiguous [16384 x 4096])
    gemm_cp<<<dim3(MPOS / 128, DDIM / 128, 1), 128, SM_TOTAL>>>(
        pG, EHDIM, W2, DDIM, out, DDIM, midx, EHDIM);

    // + sum_e gate*b2 (combine weights sum to 1 per mask)
    addb2_kernel<<<dim3(DDIM / 1024, MPOS), 256>>>(pgate, b2, midx, out);
}

// round 15
// speedup vs baseline: 1.8032x; 1.5585x over previous
#include <cuda_runtime.h>
#include <cstdint>

// Problem constants (fixed by setup_inputs)
#define LDIM 2048
#define DDIM 4096
#define KEXP 8
#define MPOS 1024
#define UPOS 1024
#define DPROJ 512
#define HHID 2048
#define EHDIM 16384   // KEXP * HHID

// ---------------------------------------------------------------------------
// Device-global scratch (no runtime allocation allowed)
// ---------------------------------------------------------------------------
__device__ float    g_A[(size_t)UPOS * EHDIM];    // anchors @ W1_top
__device__ float    g_B[(size_t)MPOS * EHDIM];    // masks   @ W1_bot
__device__ uint32_t g_G[(size_t)MPOS * EHDIM];    // tf32 bits of gated/combined gelu
__device__ uint32_t g_hM[(size_t)MPOS * DDIM];    // tf32 gathered mask rows of h
__device__ uint32_t g_hU[(size_t)UPOS * DDIM];    // tf32 gathered anchor rows of h
__device__ float    g_q[MPOS * DPROJ];
__device__ float    g_k[UPOS * DPROJ];
__device__ float    g_gate[MPOS * KEXP];
__device__ float    g_cmb[MPOS * 10];

// ---------------------------------------------------------------------------
// helpers
// ---------------------------------------------------------------------------
__device__ __forceinline__ uint32_t f2tf(float x) {
    uint32_t r;
    asm("cvt.rna.tf32.f32 %0, %1;" : "=r"(r) : "f"(x));
    return r;
}
__device__ __forceinline__ uint32_t smem_u32(const void* p) {
    uint32_t a;
    asm("{ .reg .u64 t; cvta.to.shared.u64 t, %1; cvt.u32.u64 %0, t; }" : "=r"(a) : "l"(p));
    return a;
}
__device__ __forceinline__ void cp16(uint32_t dst, const void* src) {
    asm volatile("cp.async.cg.shared.global [%0], [%1], 16;" :: "r"(dst), "l"(src));
}
#define CP_COMMIT() asm volatile("cp.async.commit_group;" ::: "memory")
#define CP_WAIT(n)  asm volatile("cp.async.wait_group %0;" :: "n"(n) : "memory")

__device__ __forceinline__ void ldsm_x4(uint32_t* r, uint32_t addr) {
    asm volatile("ldmatrix.sync.aligned.m8n8.x4.shared.b16 {%0,%1,%2,%3}, [%4];"
                 : "=r"(r[0]), "=r"(r[1]), "=r"(r[2]), "=r"(r[3]) : "r"(addr));
}

__device__ __forceinline__ void mma_tf32(float* c, const uint32_t* a, const uint32_t* b) {
    asm volatile(
        "mma.sync.aligned.m16n8k8.row.col.f32.tf32.tf32.f32 "
        "{%0,%1,%2,%3}, {%4,%5,%6,%7}, {%8,%9}, {%0,%1,%2,%3};\n"
        : "+f"(c[0]), "+f"(c[1]), "+f"(c[2]), "+f"(c[3])
        : "r"(a[0]), "r"(a[1]), "r"(a[2]), "r"(a[3]), "r"(b[0]), "r"(b[1]));
}

// smem stage layout (bytes):
//   A tile: [128 m][36 words]  rows 144 B (ldmatrix phases hit banks 4l..4l+3, CF)
//   B tile: [32 k][136 words]  rows 544 B (136 mod 32 = 8 -> banks 8tg+g, CF)
#define ALD 36
#define BLD 136
#define A_BYTES (128 * ALD * 4)          // 18432
#define B_BYTES (32 * BLD * 4)           // 17408
#define SM_STAGE (A_BYTES + B_BYTES)     // 35840
#define SM_TOTAL (3 * SM_STAGE)          // 107520

// ---------------------------------------------------------------------------
// Core tf32 GEMM tile: C[m0.., n0..] += A(m)[k] * W(k, n), K=Kdim.
// cp.async 3-stage pipeline (issues spread across ks steps), ldmatrix A loads,
// B scalar LDS + cvt; fragment registers double-buffered across ks steps.
// BM=BN=128, BK=32; 128 threads; 4 warps (2x2) each 64x64 via m16n8k8.
// ---------------------------------------------------------------------------
__device__ __forceinline__ void gemm_core(
    const uint32_t* __restrict__ Ag, int lda,
    const float* __restrict__ wbase, int ldw,
    float* __restrict__ Cg, int ldc, const int* __restrict__ rowC,
    int Kdim, int m0, int n0, char* smc)
{
    const int tid = threadIdx.x, lane = tid & 31, wid = tid >> 5;
    const uint32_t sb = smem_u32(smc);

    const int wm = (wid & 1) * 64, wn = (wid >> 1) * 64;
    const int g = lane >> 2, tg = lane & 3;

    const uint32_t aoff = (uint32_t)(wm + (lane & 15)) * (ALD * 4) + (lane >> 4) * 16;

    // A loader: rows ar+16i (i<8), 16B chunk akq
    const int ar = tid >> 3, akq = tid & 7;
    const uint32_t* aptr[8];
#pragma unroll
    for (int i = 0; i < 8; i++)
        aptr[i] = Ag + (size_t)(m0 + ar + 16 * i) * lda + akq * 4;
    // B loader: k rows bk+4i (i<8), 16B chunk bnq
    const int bk = tid >> 5, bnq = tid & 31;
    const float* bbase = wbase + (size_t)bk * ldw + bnq * 4;

// full-stage issue (prologue only)
#define ISSUE(s, kt)                                                             \
    {                                                                            \
        uint32_t ab = sb + (s) * SM_STAGE;                                       \
        _Pragma("unroll")                                                        \
        for (int i = 0; i < 8; i++)                                              \
            cp16(ab + (ar + 16 * i) * (ALD * 4) + akq * 16, aptr[i] + (kt));     \
        uint32_t bb = sb + (s) * SM_STAGE + A_BYTES;                             \
        _Pragma("unroll")                                                        \
        for (int i = 0; i < 8; i++)                                              \
            cp16(bb + (bk + 4 * i) * (BLD * 4) + bnq * 16,                       \
                 bbase + (size_t)((kt) + 4 * i) * ldw);                          \
        CP_COMMIT();                                                             \
    }

// quarter-stage issue (spread across ks steps; commit on part 3)
#define ISSUE_P(s, kt, p)                                                        \
    {                                                                            \
        uint32_t ab = sb + (s) * SM_STAGE;                                       \
        uint32_t bb = ab + A_BYTES;                                              \
        cp16(ab + (ar + 16 * (2 * (p))) * (ALD * 4) + akq * 16,                  \
             aptr[2 * (p)] + (kt));                                              \
        cp16(ab + (ar + 16 * (2 * (p) + 1)) * (ALD * 4) + akq * 16,              \
             aptr[2 * (p) + 1] + (kt));                                          \
        cp16(bb + (bk + 4 * (2 * (p))) * (BLD * 4) + bnq * 16,                   \
             bbase + (size_t)((kt) + 4 * (2 * (p))) * ldw);                      \
        cp16(bb + (bk + 4 * (2 * (p) + 1)) * (BLD * 4) + bnq * 16,               \
             bbase + (size_t)((kt) + 4 * (2 * (p) + 1)) * ldw);                  \
        if ((p) == 3) CP_COMMIT();                                               \
    }

// fragment loads for one ks step
#define LOADA(ks, arr)                                                           \
    { _Pragma("unroll")                                                          \
      for (int mf = 0; mf < 4; mf++)                                             \
          ldsm_x4((arr)[mf], abase + mf * (16 * ALD * 4) + (ks) * 32); }
#define LOADB(ks, arr)                                                           \
    { _Pragma("unroll")                                                          \
      for (int nf = 0; nf < 8; nf++) {                                           \
          int c = wn + nf * 8 + g;                                               \
          (arr)[nf][0] = f2tf(Bs[((ks) * 8 + tg) * BLD + c]);                    \
          (arr)[nf][1] = f2tf(Bs[((ks) * 8 + tg + 4) * BLD + c]);                \
      } }

    float acc[4][8][4];
#pragma unroll
    for (int i = 0; i < 4; i++)
#pragma unroll
        for (int j = 0; j < 8; j++)
#pragma unroll
            for (int c = 0; c < 4; c++) acc[i][j][c] = 0.f;

    const int KT = Kdim / 32;
    ISSUE(0, 0);
    ISSUE(1, 32);

    for (int ki = 0; ki < KT; ki++) {
        if (ki == KT - 1) { CP_WAIT(0); } else { CP_WAIT(1); }
        __syncthreads();
        const bool pre = (ki + 2 < KT);
        const int ps = (ki + 2) % 3;
        const int pk = (ki + 2) * 32;

        const uint32_t abase = sb + (ki % 3) * SM_STAGE + aoff;
        const float*   Bs = (const float*)(smc + (ki % 3) * SM_STAGE + A_BYTES);

        uint32_t a[2][4][4], b[2][8][2];
        LOADA(0, a[0]);
        LOADB(0, b[0]);
#pragma unroll
        for (int ks = 0; ks < 4; ks++) {
            const int cur = ks & 1, nxt = cur ^ 1;
            if (ks < 3) { LOADA(ks + 1, a[nxt]); LOADB(ks + 1, b[nxt]); }
            if (pre) ISSUE_P(ps, pk, ks);
#pragma unroll
            for (int mf = 0; mf < 4; mf++)
#pragma unroll
                for (int nf = 0; nf < 8; nf++)
                    mma_tf32(acc[mf][nf], a[cur][mf], b[cur][nf]);
        }
    }

#pragma unroll
    for (int mf = 0; mf < 4; mf++) {
        int r0 = m0 + wm + mf * 16 + g;
        int r1 = r0 + 8;
        size_t o0 = (size_t)(rowC ? rowC[r0] : r0) * (size_t)ldc;
        size_t o1 = (size_t)(rowC ? rowC[r1] : r1) * (size_t)ldc;
#pragma unroll
        for (int nf = 0; nf < 8; nf++) {
            int c = n0 + wn + nf * 8 + tg * 2;
            *reinterpret_cast<float2*>(Cg + o0 + c) = make_float2(acc[mf][nf][0], acc[mf][nf][1]);
            *reinterpret_cast<float2*>(Cg + o1 + c) = make_float2(acc[mf][nf][2], acc[mf][nf][3]);
        }
    }
#undef ISSUE
#undef ISSUE_P
#undef LOADA
#undef LOADB
}

// ---------------------------------------------------------------------------
// Generic GEMM (used for the final W2 GEMM, rowC = midx scatter)
// ---------------------------------------------------------------------------
__global__ __launch_bounds__(128, 2)
void gemm_cp(const uint32_t* __restrict__ Ag, int lda,
             const float* __restrict__ Wg, int ldw,
             float* __restrict__ Cg, int ldc, const int* __restrict__ rowC,
             int Kdim)
{
    extern __shared__ char smc[];
    const int m0 = blockIdx.x * 128, n0 = blockIdx.y * 128;
    gemm_core(Ag, lda, Wg + n0, ldw, Cg, ldc, rowC, Kdim, m0, n0, smc);
}

// ---------------------------------------------------------------------------
// Fused launch: z=0 -> A = hU @ W1_top ; z=1 -> B = hM @ W1_bot ;
//               z=2, y<4 -> q = hM @ Wq ; z=2, 4<=y<8 -> k = hU @ Wk.
// All slices share Kdim = DDIM = 4096.
// ---------------------------------------------------------------------------
__global__ __launch_bounds__(128, 2)
void gemm_fused(const uint32_t* __restrict__ hU, const uint32_t* __restrict__ hM,
                const float* __restrict__ W1,
                const float* __restrict__ Wq, const float* __restrict__ Wk,
                float* __restrict__ CA, float* __restrict__ CB,
                float* __restrict__ Cq, float* __restrict__ Ck)
{
    extern __shared__ char smc[];
    const int m0 = blockIdx.x * 128;
    const int z = blockIdx.z, y = blockIdx.y;
    const size_t ESTR = (size_t)2 * DDIM * HHID;

    if (z == 0) {
        int n0 = y * 128;
        const float* wb = W1 + (size_t)(n0 / HHID) * ESTR + (size_t)(n0 % HHID);
        gemm_core(hU, DDIM, wb, HHID, CA, EHDIM, nullptr, DDIM, m0, n0, smc);
    } else if (z == 1) {
        int n0 = y * 128;
        const float* wb = W1 + (size_t)DDIM * HHID
                        + (size_t)(n0 / HHID) * ESTR + (size_t)(n0 % HHID);
        gemm_core(hM, DDIM, wb, HHID, CB, EHDIM, nullptr, DDIM, m0, n0, smc);
    } else {
        if (y < 4) {
            int n0 = y * 128;
            gemm_core(hM, DDIM, Wq + n0, DPROJ, Cq, DPROJ, nullptr, DDIM, m0, n0, smc);
        } else if (y < 8) {
            int n0 = (y - 4) * 128;
            gemm_core(hU, DDIM, Wk + n0, DPROJ, Ck, DPROJ, nullptr, DDIM, m0, n0, smc);
        }
        // y >= 8: immediate exit
    }
}

// ---------------------------------------------------------------------------
// gather h rows by index + convert to tf32 bits; optionally (gate != nullptr)
// also compute gate[r,:] = softmax(h_row @ Wr + br) in the same pass.
// ---------------------------------------------------------------------------
__global__ void gather_gate(const float* __restrict__ h, const int* __restrict__ idx,
                            uint32_t* __restrict__ dst,
                            const float* __restrict__ Wr, const float* __restrict__ br,
                            float* __restrict__ gate)
{
    const int r = blockIdx.x;
    const int tid = threadIdx.x;
    const float4* s = reinterpret_cast<const float4*>(h + (size_t)idx[r] * DDIM);
    uint4* d = reinterpret_cast<uint4*>(dst + (size_t)r * DDIM);

    float acc[KEXP];
#pragma unroll
    for (int e = 0; e < KEXP; e++) acc[e] = 0.f;

    for (int i = tid; i < DDIM / 4; i += 256) {
        float4 v = s[i];
        uint4 o;
        o.x = f2tf(v.x); o.y = f2tf(v.y); o.z = f2tf(v.z); o.w = f2tf(v.w);
        d[i] = o;
        if (gate) {
            const float4* wr = reinterpret_cast<const float4*>(Wr + (size_t)(4 * i) * KEXP);
            float hv[4] = {v.x, v.y, v.z, v.w};
#pragma unroll
            for (int dd = 0; dd < 4; dd++) {
                float4 w0 = wr[2 * dd], w1 = wr[2 * dd + 1];
                acc[0] += hv[dd] * w0.x; acc[1] += hv[dd] * w0.y;
                acc[2] += hv[dd] * w0.z; acc[3] += hv[dd] * w0.w;
                acc[4] += hv[dd] * w1.x; acc[5] += hv[dd] * w1.y;
                acc[6] += hv[dd] * w1.z; acc[7] += hv[dd] * w1.w;
            }
        }
    }
    if (!gate) return;

#pragma unroll
    for (int off = 16; off > 0; off >>= 1)
#pragma unroll
        for (int e = 0; e < KEXP; e++)
            acc[e] += __shfl_down_sync(0xffffffffu, acc[e], off);

    __shared__ float ws[8][KEXP];
    const int w = tid >> 5, lane = tid & 31;
    if (lane == 0)
#pragma unroll
        for (int e = 0; e < KEXP; e++) ws[w][e] = acc[e];
    __syncthreads();
    if (tid == 0) {
        float l[KEXP];
#pragma unroll
        for (int e = 0; e < KEXP; e++) {
            float s2 = br[e];
#pragma unroll
            for (int ww = 0; ww < 8; ww++) s2 += ws[ww][e];
            l[e] = s2;
        }
        float mx = l[0];
#pragma unroll
        for (int e = 1; e < KEXP; e++) mx = fmaxf(mx, l[e]);
        float sum = 0.f;
#pragma unroll
        for (int e = 0; e < KEXP; e++) { l[e] = expf(l[e] - mx); sum += l[e]; }
        float inv = 1.f / sum;
#pragma unroll
        for (int e = 0; e < KEXP; e++) gate[r * KEXP + e] = l[e] * inv;
    }
}

// ---------------------------------------------------------------------------
// per-mask pair scores + segment softmax (anchors u = m-5 .. m+4 in [0,UPOS))
// ---------------------------------------------------------------------------
__global__ void score_combine(const float* __restrict__ q, const float* __restrict__ k,
                              const float* __restrict__ bq, const float* __restrict__ bk,
                              float* __restrict__ cmb)
{
    const int m = blockIdx.x;
    const int w = threadIdx.x >> 5;    // 0..9
    const int lane = threadIdx.x & 31;
    const int u = m - 5 + w;
    const bool valid = (u >= 0) && (u < UPOS);

    __shared__ float sc[10];
    float s = 0.f;
    if (valid) {
        const float* qp = q + (size_t)m * DPROJ;
        const float* kp = k + (size_t)u * DPROJ;
        for (int i = lane; i < DPROJ; i += 32)
            s += (qp[i] + bq[i]) * (kp[i] + bk[i]);
#pragma unroll
        for (int off = 16; off > 0; off >>= 1)
            s += __shfl_down_sync(0xffffffffu, s, off);
    }
    if (lane == 0) sc[w] = valid ? s * 0.044194173824159216f : -1e30f;
    __syncthreads();
    if (threadIdx.x == 0) {
        float mx = -1e30f;
#pragma unroll
        for (int j = 0; j < 10; j++) mx = fmaxf(mx, sc[j]);
        float e[10]; float sum = 0.f;
#pragma unroll
        for (int j = 0; j < 10; j++) {
            e[j] = (sc[j] > -1e29f) ? expf(sc[j] - mx) : 0.f;
            sum += e[j];
        }
        float inv = 1.f / fmaxf(sum, 1e-8f);
#pragma unroll
        for (int j = 0; j < 10; j++) cmb[m * 10 + j] = e[j] * inv;
    }
}

// ---------------------------------------------------------------------------
// g_G[m, n] = tf32( gate[m][n/H] * sum_j cmb[m][j] * gelu(A[u_j,n]+B[m,n]+b1[n]) )
// float4-vectorized: each thread handles 4 consecutive n.
// ---------------------------------------------------------------------------
__global__ void aggregate_kernel(const float* __restrict__ A, const float* __restrict__ B,
                                 const float* __restrict__ b1, const float* __restrict__ cmb,
                                 const float* __restrict__ gate, uint32_t* __restrict__ G)
{
    const int m = blockIdx.y;
    const int n4 = blockIdx.x * 256 + threadIdx.x;   // float4 index
    const int n = n4 * 4;
    __shared__ float c[10];
    __shared__ int   us[10];
    __shared__ float gt[KEXP];
    if (threadIdx.x < 10) {
        c[threadIdx.x] = cmb[m * 10 + threadIdx.x];
        int u = m - 5 + threadIdx.x;
        us[threadIdx.x] = min(max(u, 0), UPOS - 1);
    }
    if (threadIdx.x < KEXP) gt[threadIdx.x] = gate[m * KEXP + threadIdx.x];
    __syncthreads();

    const float4 Bq = reinterpret_cast<const float4*>(B + (size_t)m * EHDIM)[n4];
    const float4 b1q = reinterpret_cast<const float4*>(b1)[n4];
    float Bv[4] = {Bq.x + b1q.x, Bq.y + b1q.y, Bq.z + b1q.z, Bq.w + b1q.w};
    float acc[4] = {0.f, 0.f, 0.f, 0.f};
#pragma unroll
    for (int j = 0; j < 10; j++) {
        const float4 Aq = reinterpret_cast<const float4*>(A + (size_t)us[j] * EHDIM)[n4];
        float av[4] = {Aq.x, Aq.y, Aq.z, Aq.w};
#pragma unroll
        for (int d = 0; d < 4; d++) {
            float x = av[d] + Bv[d];
            float ge = 0.5f * x * (1.f + erff(x * 0.70710678118654752f));
            acc[d] = fmaf(c[j], ge, acc[d]);
        }
    }
    const float gv = gt[n >> 11];  // 4 consecutive n share the expert (4 | 2048)
    uint4 o;
    o.x = f2tf(gv * acc[0]); o.y = f2tf(gv * acc[1]);
    o.z = f2tf(gv * acc[2]); o.w = f2tf(gv * acc[3]);
    reinterpret_cast<uint4*>(G + (size_t)m * EHDIM)[n4] = o;
}

// out[midx[m], d..d+3] += sum_e gate[m][e] * b2[e][d..d+3]
__global__ void addb2_kernel(const float* __restrict__ gate, const float* __restrict__ b2,
                             const int* __restrict__ midx, float* __restrict__ out)
{
    const int m = blockIdx.y;
    const int d4 = blockIdx.x * 256 + threadIdx.x;
    float4 s = make_float4(0.f, 0.f, 0.f, 0.f);
#pragma unroll
    for (int e = 0; e < KEXP; e++) {
        float ge = gate[m * KEXP + e];
        float4 bq = reinterpret_cast<const float4*>(b2 + (size_t)e * DDIM)[d4];
        s.x = fmaf(ge, bq.x, s.x); s.y = fmaf(ge, bq.y, s.y);
        s.z = fmaf(ge, bq.z, s.z); s.w = fmaf(ge, bq.w, s.w);
    }
    float4* op = &reinterpret_cast<float4*>(out + (size_t)midx[m] * DDIM)[d4];
    float4 cur = *op;
    cur.x += s.x; cur.y += s.y; cur.z += s.z; cur.w += s.w;
    *op = cur;
}

// ---------------------------------------------------------------------------
extern "C" void kernel_launch(void* const* d_in, const int* in_sizes, int n_in,
                              void* d_out, int out_size)
{
    const float* h   = (const float*)d_in[0];
    const int*   midx= (const int*)d_in[1];
    const int*   uidx= (const int*)d_in[2];
    const float* Wr  = (const float*)d_in[4];
    const float* br  = (const float*)d_in[5];
    const float* W1  = (const float*)d_in[6];
    const float* b1  = (const float*)d_in[7];
    const float* W2  = (const float*)d_in[8];
    const float* b2  = (const float*)d_in[9];
    const float* Wq  = (const float*)d_in[10];
    const float* bq  = (const float*)d_in[11];
    const float* Wk  = (const float*)d_in[12];
    const float* bk  = (const float*)d_in[13];
    float* out = (float*)d_out;

    float *pA, *pB, *pq, *pk, *pgate, *pcmb;
    uint32_t *pG, *phM, *phU;
    cudaGetSymbolAddress((void**)&pA, g_A);
    cudaGetSymbolAddress((void**)&pB, g_B);
    cudaGetSymbolAddress((void**)&pG, g_G);
    cudaGetSymbolAddress((void**)&phM, g_hM);
    cudaGetSymbolAddress((void**)&phU, g_hU);
    cudaGetSymbolAddress((void**)&pq, g_q);
    cudaGetSymbolAddress((void**)&pk, g_k);
    cudaGetSymbolAddress((void**)&pgate, g_gate);
    cudaGetSymbolAddress((void**)&pcmb, g_cmb);

    cudaFuncSetAttribute(gemm_cp, cudaFuncAttributeMaxDynamicSharedMemorySize, SM_TOTAL);
    cudaFuncSetAttribute(gemm_fused, cudaFuncAttributeMaxDynamicSharedMemorySize, SM_TOTAL);

    // zero output (odd rows stay zero; even rows overwritten by final GEMM)
    cudaMemsetAsync(out, 0, (size_t)out_size * sizeof(float));

    // gather + convert h rows; mask variant also computes the gate softmax
    gather_gate<<<MPOS, 256>>>(h, midx, phM, Wr, br, pgate);
    gather_gate<<<UPOS, 256>>>(h, uidx, phU, nullptr, nullptr, nullptr);

    // Fused: z=0 -> A = hU @ W1_top ; z=1 -> B = hM @ W1_bot ; z=2 -> q/k GEMMs
    gemm_fused<<<dim3(MPOS / 128, EHDIM / 128, 3), 128, SM_TOTAL>>>(
        phU, phM, W1, Wq, Wk, pA, pB, pq, pk);

    // per-mask segment softmax over <=10 anchors
    score_combine<<<MPOS, 320>>>(pq, pk, bq, bk, pcmb);

    // gelu + combine aggregation, gate folded in, tf32 output (float4)
    aggregate_kernel<<<dim3(EHDIM / 1024, MPOS), 256>>>(pA, pB, b1, pcmb, pgate, pG);

    // out[masks] = G @ W2_flat   (K = 16384, W2 flat contiguous [16384 x 4096])
    gemm_cp<<<dim3(MPOS / 128, DDIM / 128, 1), 128, SM_TOTAL>>>(
        pG, EHDIM, W2, DDIM, out, DDIM, midx, EHDIM);

    // + sum_e gate*b2 (combine weights sum to 1 per mask)
    addb2_kernel<<<dim3(DDIM / 1024, MPOS), 256>>>(pgate, b2, midx, out);
}

// round 16
// speedup vs baseline: 1.8113x; 1.0045x over previous
#include <cuda_runtime.h>
#include <cstdint>

// Problem constants (fixed by setup_inputs)
#define LDIM 2048
#define DDIM 4096
#define KEXP 8
#define MPOS 1024
#define UPOS 1024
#define DPROJ 512
#define HHID 2048
#define EHDIM 16384   // KEXP * HHID

// ---------------------------------------------------------------------------
// Device-global scratch (no runtime allocation allowed)
// ---------------------------------------------------------------------------
__device__ float    g_A[(size_t)UPOS * EHDIM];    // anchors @ W1_top
__device__ float    g_B[(size_t)MPOS * EHDIM];    // masks   @ W1_bot
__device__ uint32_t g_G[(size_t)MPOS * EHDIM];    // tf32 bits of gated/combined gelu
__device__ uint32_t g_hM[(size_t)MPOS * DDIM];    // tf32 gathered mask rows of h
__device__ uint32_t g_hU[(size_t)UPOS * DDIM];    // tf32 gathered anchor rows of h
__device__ float    g_q[MPOS * DPROJ];
__device__ float    g_k[UPOS * DPROJ];
__device__ float    g_gate[MPOS * KEXP];
__device__ float    g_cmb[MPOS * 10];

// ---------------------------------------------------------------------------
// helpers
// ---------------------------------------------------------------------------
__device__ __forceinline__ uint32_t f2tf(float x) {
    uint32_t r;
    asm("cvt.rna.tf32.f32 %0, %1;" : "=r"(r) : "f"(x));
    return r;
}
__device__ __forceinline__ uint32_t smem_u32(const void* p) {
    uint32_t a;
    asm("{ .reg .u64 t; cvta.to.shared.u64 t, %1; cvt.u32.u64 %0, t; }" : "=r"(a) : "l"(p));
    return a;
}
__device__ __forceinline__ void cp16(uint32_t dst, const void* src) {
    asm volatile("cp.async.cg.shared.global [%0], [%1], 16;" :: "r"(dst), "l"(src));
}
#define CP_COMMIT() asm volatile("cp.async.commit_group;" ::: "memory")
#define CP_WAIT(n)  asm volatile("cp.async.wait_group %0;" :: "n"(n) : "memory")

__device__ __forceinline__ void ldsm_x4(uint32_t* r, uint32_t addr) {
    asm volatile("ldmatrix.sync.aligned.m8n8.x4.shared.b16 {%0,%1,%2,%3}, [%4];"
                 : "=r"(r[0]), "=r"(r[1]), "=r"(r[2]), "=r"(r[3]) : "r"(addr));
}

__device__ __forceinline__ void mma_tf32(float* c, const uint32_t* a, const uint32_t* b) {
    asm volatile(
        "mma.sync.aligned.m16n8k8.row.col.f32.tf32.tf32.f32 "
        "{%0,%1,%2,%3}, {%4,%5,%6,%7}, {%8,%9}, {%0,%1,%2,%3};\n"
        : "+f"(c[0]), "+f"(c[1]), "+f"(c[2]), "+f"(c[3])
        : "r"(a[0]), "r"(a[1]), "r"(a[2]), "r"(a[3]), "r"(b[0]), "r"(b[1]));
}

// smem stage layout (bytes):
//   A tile: [128 m][36 words]  rows 144 B (ldmatrix phases hit banks 4l..4l+3, CF)
//   B tile: [32 k][136 words]  rows 544 B (136 mod 32 = 8 -> banks 8tg+g, CF)
#define ALD 36
#define BLD 136
#define A_BYTES (128 * ALD * 4)          // 18432
#define B_BYTES (32 * BLD * 4)           // 17408
#define SM_STAGE (A_BYTES + B_BYTES)     // 35840
#define SM_TOTAL (3 * SM_STAGE)          // 107520

// ---------------------------------------------------------------------------
// Core tf32 GEMM tile: C[m0.., n0..] += A(m)[k] * W(k, n), K=Kdim.
// cp.async 3-stage pipeline (issues spread across ks steps), ldmatrix A loads,
// B scalar LDS + cvt; fragment registers double-buffered across ks steps.
// BM=BN=128, BK=32; 128 threads; 4 warps (2x2) each 64x64 via m16n8k8.
// ---------------------------------------------------------------------------
__device__ __forceinline__ void gemm_core(
    const uint32_t* __restrict__ Ag, int lda,
    const float* __restrict__ wbase, int ldw,
    float* __restrict__ Cg, int ldc, const int* __restrict__ rowC,
    int Kdim, int m0, int n0, char* smc)
{
    const int tid = threadIdx.x, lane = tid & 31, wid = tid >> 5;
    const uint32_t sb = smem_u32(smc);

    const int wm = (wid & 1) * 64, wn = (wid >> 1) * 64;
    const int g = lane >> 2, tg = lane & 3;

    const uint32_t aoff = (uint32_t)(wm + (lane & 15)) * (ALD * 4) + (lane >> 4) * 16;

    // A loader: rows ar+16i (i<8), 16B chunk akq
    const int ar = tid >> 3, akq = tid & 7;
    const uint32_t* aptr[8];
#pragma unroll
    for (int i = 0; i < 8; i++)
        aptr[i] = Ag + (size_t)(m0 + ar + 16 * i) * lda + akq * 4;
    // B loader: k rows bk+4i (i<8), 16B chunk bnq
    const int bk = tid >> 5, bnq = tid & 31;
    const float* bbase = wbase + (size_t)bk * ldw + bnq * 4;

// full-stage issue (prologue only)
#define ISSUE(s, kt)                                                             \
    {                                                                            \
        uint32_t ab = sb + (s) * SM_STAGE;                                       \
        _Pragma("unroll")                                                        \
        for (int i = 0; i < 8; i++)                                              \
            cp16(ab + (ar + 16 * i) * (ALD * 4) + akq * 16, aptr[i] + (kt));     \
        uint32_t bb = sb + (s) * SM_STAGE + A_BYTES;                             \
        _Pragma("unroll")                                                        \
        for (int i = 0; i < 8; i++)                                              \
            cp16(bb + (bk + 4 * i) * (BLD * 4) + bnq * 16,                       \
                 bbase + (size_t)((kt) + 4 * i) * ldw);                          \
        CP_COMMIT();                                                             \
    }

// quarter-stage issue (spread across ks steps; commit on part 3)
#define ISSUE_P(s, kt, p)                                                        \
    {                                                                            \
        uint32_t ab = sb + (s) * SM_STAGE;                                       \
        uint32_t bb = ab + A_BYTES;                                              \
        cp16(ab + (ar + 16 * (2 * (p))) * (ALD * 4) + akq * 16,                  \
             aptr[2 * (p)] + (kt));                                              \
        cp16(ab + (ar + 16 * (2 * (p) + 1)) * (ALD * 4) + akq * 16,              \
             aptr[2 * (p) + 1] + (kt));                                          \
        cp16(bb + (bk + 4 * (2 * (p))) * (BLD * 4) + bnq * 16,                   \
             bbase + (size_t)((kt) + 4 * (2 * (p))) * ldw);                      \
        cp16(bb + (bk + 4 * (2 * (p) + 1)) * (BLD * 4) + bnq * 16,               \
             bbase + (size_t)((kt) + 4 * (2 * (p) + 1)) * ldw);                  \
        if ((p) == 3) CP_COMMIT();                                               \
    }

// fragment loads for one ks step
#define LOADA(ks, arr)                                                           \
    { _Pragma("unroll")                                                          \
      for (int mf = 0; mf < 4; mf++)                                             \
          ldsm_x4((arr)[mf], abase + mf * (16 * ALD * 4) + (ks) * 32); }
#define LOADB(ks, arr)                                                           \
    { _Pragma("unroll")                                                          \
      for (int nf = 0; nf < 8; nf++) {                                           \
          int c = wn + nf * 8 + g;                                               \
          (arr)[nf][0] = f2tf(Bs[((ks) * 8 + tg) * BLD + c]);                    \
          (arr)[nf][1] = f2tf(Bs[((ks) * 8 + tg + 4) * BLD + c]);                \
      } }

    float acc[4][8][4];
#pragma unroll
    for (int i = 0; i < 4; i++)
#pragma unroll
        for (int j = 0; j < 8; j++)
#pragma unroll
            for (int c = 0; c < 4; c++) acc[i][j][c] = 0.f;

    const int KT = Kdim / 32;
    ISSUE(0, 0);
    ISSUE(1, 32);

    for (int ki = 0; ki < KT; ki++) {
        if (ki == KT - 1) { CP_WAIT(0); } else { CP_WAIT(1); }
        __syncthreads();
        const bool pre = (ki + 2 < KT);
        const int ps = (ki + 2) % 3;
        const int pk = (ki + 2) * 32;

        const uint32_t abase = sb + (ki % 3) * SM_STAGE + aoff;
        const float*   Bs = (const float*)(smc + (ki % 3) * SM_STAGE + A_BYTES);

        uint32_t a[2][4][4], b[2][8][2];
        LOADA(0, a[0]);
        LOADB(0, b[0]);
#pragma unroll
        for (int ks = 0; ks < 4; ks++) {
            const int cur = ks & 1, nxt = cur ^ 1;
            if (ks < 3) { LOADA(ks + 1, a[nxt]); LOADB(ks + 1, b[nxt]); }
            if (pre) ISSUE_P(ps, pk, ks);
#pragma unroll
            for (int mf = 0; mf < 4; mf++)
#pragma unroll
                for (int nf = 0; nf < 8; nf++)
                    mma_tf32(acc[mf][nf], a[cur][mf], b[cur][nf]);
        }
    }

#pragma unroll
    for (int mf = 0; mf < 4; mf++) {
        int r0 = m0 + wm + mf * 16 + g;
        int r1 = r0 + 8;
        size_t o0 = (size_t)(rowC ? rowC[r0] : r0) * (size_t)ldc;
        size_t o1 = (size_t)(rowC ? rowC[r1] : r1) * (size_t)ldc;
#pragma unroll
        for (int nf = 0; nf < 8; nf++) {
            int c = n0 + wn + nf * 8 + tg * 2;
            *reinterpret_cast<float2*>(Cg + o0 + c) = make_float2(acc[mf][nf][0], acc[mf][nf][1]);
            *reinterpret_cast<float2*>(Cg + o1 + c) = make_float2(acc[mf][nf][2], acc[mf][nf][3]);
        }
    }
#undef ISSUE
#undef ISSUE_P
#undef LOADA
#undef LOADB
}

// ---------------------------------------------------------------------------
// Generic GEMM (used for the final W2 GEMM, rowC = midx scatter)
// ---------------------------------------------------------------------------
__global__ __launch_bounds__(128, 2)
void gemm_cp(const uint32_t* __restrict__ Ag, int lda,
             const float* __restrict__ Wg, int ldw,
             float* __restrict__ Cg, int ldc, const int* __restrict__ rowC,
             int Kdim)
{
    extern __shared__ char smc[];
    const int m0 = blockIdx.x * 128, n0 = blockIdx.y * 128;
    gemm_core(Ag, lda, Wg + n0, ldw, Cg, ldc, rowC, Kdim, m0, n0, smc);
}

// ---------------------------------------------------------------------------
// Fused launch: z=0 -> A = hU @ W1_top ; z=1 -> B = hM @ W1_bot ;
//               z=2, y<4 -> q = hM @ Wq ; z=2, 4<=y<8 -> k = hU @ Wk.
// All slices share Kdim = DDIM = 4096.
// ---------------------------------------------------------------------------
__global__ __launch_bounds__(128, 2)
void gemm_fused(const uint32_t* __restrict__ hU, const uint32_t* __restrict__ hM,
                const float* __restrict__ W1,
                const float* __restrict__ Wq, const float* __restrict__ Wk,
                float* __restrict__ CA, float* __restrict__ CB,
                float* __restrict__ Cq, float* __restrict__ Ck)
{
    extern __shared__ char smc[];
    const int m0 = blockIdx.x * 128;
    const int z = blockIdx.z, y = blockIdx.y;
    const size_t ESTR = (size_t)2 * DDIM * HHID;

    if (z == 0) {
        int n0 = y * 128;
        const float* wb = W1 + (size_t)(n0 / HHID) * ESTR + (size_t)(n0 % HHID);
        gemm_core(hU, DDIM, wb, HHID, CA, EHDIM, nullptr, DDIM, m0, n0, smc);
    } else if (z == 1) {
        int n0 = y * 128;
        const float* wb = W1 + (size_t)DDIM * HHID
                        + (size_t)(n0 / HHID) * ESTR + (size_t)(n0 % HHID);
        gemm_core(hM, DDIM, wb, HHID, CB, EHDIM, nullptr, DDIM, m0, n0, smc);
    } else {
        if (y < 4) {
            int n0 = y * 128;
            gemm_core(hM, DDIM, Wq + n0, DPROJ, Cq, DPROJ, nullptr, DDIM, m0, n0, smc);
        } else if (y < 8) {
            int n0 = (y - 4) * 128;
            gemm_core(hU, DDIM, Wk + n0, DPROJ, Ck, DPROJ, nullptr, DDIM, m0, n0, smc);
        }
        // y >= 8: immediate exit
    }
}

// ---------------------------------------------------------------------------
// gather h rows by index + convert to tf32 bits; optionally (gate != nullptr)
// also compute gate[r,:] = softmax(h_row @ Wr + br) in the same pass.
// ---------------------------------------------------------------------------
__global__ void gather_gate(const float* __restrict__ h, const int* __restrict__ idx,
                            uint32_t* __restrict__ dst,
                            const float* __restrict__ Wr, const float* __restrict__ br,
                            float* __restrict__ gate)
{
    const int r = blockIdx.x;
    const int tid = threadIdx.x;
    const float4* s = reinterpret_cast<const float4*>(h + (size_t)idx[r] * DDIM);
    uint4* d = reinterpret_cast<uint4*>(dst + (size_t)r * DDIM);

    float acc[KEXP];
#pragma unroll
    for (int e = 0; e < KEXP; e++) acc[e] = 0.f;

    for (int i = tid; i < DDIM / 4; i += 256) {
        float4 v = s[i];
        uint4 o;
        o.x = f2tf(v.x); o.y = f2tf(v.y); o.z = f2tf(v.z); o.w = f2tf(v.w);
        d[i] = o;
        if (gate) {
            const float4* wr = reinterpret_cast<const float4*>(Wr + (size_t)(4 * i) * KEXP);
            float hv[4] = {v.x, v.y, v.z, v.w};
#pragma unroll
            for (int dd = 0; dd < 4; dd++) {
                float4 w0 = wr[2 * dd], w1 = wr[2 * dd + 1];
                acc[0] += hv[dd] * w0.x; acc[1] += hv[dd] * w0.y;
                acc[2] += hv[dd] * w0.z; acc[3] += hv[dd] * w0.w;
                acc[4] += hv[dd] * w1.x; acc[5] += hv[dd] * w1.y;
                acc[6] += hv[dd] * w1.z; acc[7] += hv[dd] * w1.w;
            }
        }
    }
    if (!gate) return;

#pragma unroll
    for (int off = 16; off > 0; off >>= 1)
#pragma unroll
        for (int e = 0; e < KEXP; e++)
            acc[e] += __shfl_down_sync(0xffffffffu, acc[e], off);

    __shared__ float ws[8][KEXP];
    const int w = tid >> 5, lane = tid & 31;
    if (lane == 0)
#pragma unroll
        for (int e = 0; e < KEXP; e++) ws[w][e] = acc[e];
    __syncthreads();
    if (tid == 0) {
        float l[KEXP];
#pragma unroll
        for (int e = 0; e < KEXP; e++) {
            float s2 = br[e];
#pragma unroll
            for (int ww = 0; ww < 8; ww++) s2 += ws[ww][e];
            l[e] = s2;
        }
        float mx = l[0];
#pragma unroll
        for (int e = 1; e < KEXP; e++) mx = fmaxf(mx, l[e]);
        float sum = 0.f;
#pragma unroll
        for (int e = 0; e < KEXP; e++) { l[e] = expf(l[e] - mx); sum += l[e]; }
        float inv = 1.f / sum;
#pragma unroll
        for (int e = 0; e < KEXP; e++) gate[r * KEXP + e] = l[e] * inv;
    }
}

// ---------------------------------------------------------------------------
// per-mask pair scores + segment softmax (anchors u = m-5 .. m+4 in [0,UPOS))
// float4 dot products.
// ---------------------------------------------------------------------------
__global__ void score_combine(const float* __restrict__ q, const float* __restrict__ k,
                              const float* __restrict__ bq, const float* __restrict__ bk,
                              float* __restrict__ cmb)
{
    const int m = blockIdx.x;
    const int w = threadIdx.x >> 5;    // 0..9
    const int lane = threadIdx.x & 31;
    const int u = m - 5 + w;
    const bool valid = (u >= 0) && (u < UPOS);

    __shared__ float sc[10];
    float s = 0.f;
    if (valid) {
        const float4* qp = reinterpret_cast<const float4*>(q + (size_t)m * DPROJ);
        const float4* kp = reinterpret_cast<const float4*>(k + (size_t)u * DPROJ);
        const float4* bqp = reinterpret_cast<const float4*>(bq);
        const float4* bkp = reinterpret_cast<const float4*>(bk);
#pragma unroll
        for (int i = lane; i < DPROJ / 4; i += 32) {
            float4 qv = qp[i], kv = kp[i], bqv = bqp[i], bkv = bkp[i];
            s += (qv.x + bqv.x) * (kv.x + bkv.x);
            s += (qv.y + bqv.y) * (kv.y + bkv.y);
            s += (qv.z + bqv.z) * (kv.z + bkv.z);
            s += (qv.w + bqv.w) * (kv.w + bkv.w);
        }
#pragma unroll
        for (int off = 16; off > 0; off >>= 1)
            s += __shfl_down_sync(0xffffffffu, s, off);
    }
    if (lane == 0) sc[w] = valid ? s * 0.044194173824159216f : -1e30f;
    __syncthreads();
    if (threadIdx.x == 0) {
        float mx = -1e30f;
#pragma unroll
        for (int j = 0; j < 10; j++) mx = fmaxf(mx, sc[j]);
        float e[10]; float sum = 0.f;
#pragma unroll
        for (int j = 0; j < 10; j++) {
            e[j] = (sc[j] > -1e29f) ? expf(sc[j] - mx) : 0.f;
            sum += e[j];
        }
        float inv = 1.f / fmaxf(sum, 1e-8f);
#pragma unroll
        for (int j = 0; j < 10; j++) cmb[m * 10 + j] = e[j] * inv;
    }
}

// ---------------------------------------------------------------------------
// g_G[m, n] = tf32( gate[m][n/H] * sum_j cmb[m][j] * gelu(A[u_j,n]+B[m,n]+b1[n]) )
// float4-vectorized: each thread handles 4 consecutive n.
// ---------------------------------------------------------------------------
__global__ void aggregate_kernel(const float* __restrict__ A, const float* __restrict__ B,
                                 const float* __restrict__ b1, const float* __restrict__ cmb,
                                 const float* __restrict__ gate, uint32_t* __restrict__ G)
{
    const int m = blockIdx.y;
    const int n4 = blockIdx.x * 256 + threadIdx.x;   // float4 index
    const int n = n4 * 4;
    __shared__ float c[10];
    __shared__ int   us[10];
    __shared__ float gt[KEXP];
    if (threadIdx.x < 10) {
        c[threadIdx.x] = cmb[m * 10 + threadIdx.x];
        int u = m - 5 + threadIdx.x;
        us[threadIdx.x] = min(max(u, 0), UPOS - 1);
    }
    if (threadIdx.x < KEXP) gt[threadIdx.x] = gate[m * KEXP + threadIdx.x];
    __syncthreads();

    const float4 Bq = reinterpret_cast<const float4*>(B + (size_t)m * EHDIM)[n4];
    const float4 b1q = reinterpret_cast<const float4*>(b1)[n4];
    float Bv[4] = {Bq.x + b1q.x, Bq.y + b1q.y, Bq.z + b1q.z, Bq.w + b1q.w};
    float acc[4] = {0.f, 0.f, 0.f, 0.f};
#pragma unroll
    for (int j = 0; j < 10; j++) {
        const float4 Aq = reinterpret_cast<const float4*>(A + (size_t)us[j] * EHDIM)[n4];
        float av[4] = {Aq.x, Aq.y, Aq.z, Aq.w};
#pragma unroll
        for (int d = 0; d < 4; d++) {
            float x = av[d] + Bv[d];
            float ge = 0.5f * x * (1.f + erff(x * 0.70710678118654752f));
            acc[d] = fmaf(c[j], ge, acc[d]);
        }
    }
    const float gv = gt[n >> 11];  // 4 consecutive n share the expert (4 | 2048)
    uint4 o;
    o.x = f2tf(gv * acc[0]); o.y = f2tf(gv * acc[1]);
    o.z = f2tf(gv * acc[2]); o.w = f2tf(gv * acc[3]);
    reinterpret_cast<uint4*>(G + (size_t)m * EHDIM)[n4] = o;
}

// out[midx[m], d..d+3] += sum_e gate[m][e] * b2[e][d..d+3]
__global__ void addb2_kernel(const float* __restrict__ gate, const float* __restrict__ b2,
                             const int* __restrict__ midx, float* __restrict__ out)
{
    const int m = blockIdx.y;
    const int d4 = blockIdx.x * 256 + threadIdx.x;
    float4 s = make_float4(0.f, 0.f, 0.f, 0.f);
#pragma unroll
    for (int e = 0; e < KEXP; e++) {
        float ge = gate[m * KEXP + e];
        float4 bq = reinterpret_cast<const float4*>(b2 + (size_t)e * DDIM)[d4];
        s.x = fmaf(ge, bq.x, s.x); s.y = fmaf(ge, bq.y, s.y);
        s.z = fmaf(ge, bq.z, s.z); s.w = fmaf(ge, bq.w, s.w);
    }
    float4* op = &reinterpret_cast<float4*>(out + (size_t)midx[m] * DDIM)[d4];
    float4 cur = *op;
    cur.x += s.x; cur.y += s.y; cur.z += s.z; cur.w += s.w;
    *op = cur;
}

// ---------------------------------------------------------------------------
extern "C" void kernel_launch(void* const* d_in, const int* in_sizes, int n_in,
                              void* d_out, int out_size)
{
    const float* h   = (const float*)d_in[0];
    const int*   midx= (const int*)d_in[1];
    const int*   uidx= (const int*)d_in[2];
    const float* Wr  = (const float*)d_in[4];
    const float* br  = (const float*)d_in[5];
    const float* W1  = (const float*)d_in[6];
    const float* b1  = (const float*)d_in[7];
    const float* W2  = (const float*)d_in[8];
    const float* b2  = (const float*)d_in[9];
    const float* Wq  = (const float*)d_in[10];
    const float* bq  = (const float*)d_in[11];
    const float* Wk  = (const float*)d_in[12];
    const float* bk  = (const float*)d_in[13];
    float* out = (float*)d_out;

    float *pA, *pB, *pq, *pk, *pgate, *pcmb;
    uint32_t *pG, *phM, *phU;
    cudaGetSymbolAddress((void**)&pA, g_A);
    cudaGetSymbolAddress((void**)&pB, g_B);
    cudaGetSymbolAddress((void**)&pG, g_G);
    cudaGetSymbolAddress((void**)&phM, g_hM);
    cudaGetSymbolAddress((void**)&phU, g_hU);
    cudaGetSymbolAddress((void**)&pq, g_q);
    cudaGetSymbolAddress((void**)&pk, g_k);
    cudaGetSymbolAddress((void**)&pgate, g_gate);
    cudaGetSymbolAddress((void**)&pcmb, g_cmb);

    cudaFuncSetAttribute(gemm_cp, cudaFuncAttributeMaxDynamicSharedMemorySize, SM_TOTAL);
    cudaFuncSetAttribute(gemm_fused, cudaFuncAttributeMaxDynamicSharedMemorySize, SM_TOTAL);

    // zero output (odd rows stay zero; even rows overwritten by final GEMM)
    cudaMemsetAsync(out, 0, (size_t)out_size * sizeof(float));

    // gather + convert h rows; mask variant also computes the gate softmax
    gather_gate<<<MPOS, 256>>>(h, midx, phM, Wr, br, pgate);
    gather_gate<<<UPOS, 256>>>(h, uidx, phU, nullptr, nullptr, nullptr);

    // Fused: z=0 -> A = hU @ W1_top ; z=1 -> B = hM @ W1_bot ; z=2 -> q/k GEMMs
    gemm_fused<<<dim3(MPOS / 128, EHDIM / 128, 3), 128, SM_TOTAL>>>(
        phU, phM, W1, Wq, Wk, pA, pB, pq, pk);

    // per-mask segment softmax over <=10 anchors
    score_combine<<<MPOS, 320>>>(pq, pk, bq, bk, pcmb);

    // gelu + combine aggregation, gate folded in, tf32 output (float4)
    aggregate_kernel<<<dim3(EHDIM / 1024, MPOS), 256>>>(pA, pB, b1, pcmb, pgate, pG);

    // out[masks] = G @ W2_flat   (K = 16384, W2 flat contiguous [16384 x 4096])
    gemm_cp<<<dim3(MPOS / 128, DDIM / 128, 1), 128, SM_TOTAL>>>(
        pG, EHDIM, W2, DDIM, out, DDIM, midx, EHDIM);

    // + sum_e gate*b2 (combine weights sum to 1 per mask)
    addb2_kernel<<<dim3(DDIM / 1024, MPOS), 256>>>(pgate, b2, midx, out);
}